// round 3
// baseline (speedup 1.0000x reference)
#include <cuda_runtime.h>
#include <cuda_bf16.h>
#include <cfloat>

// Problem constants
#define NN   256      // nodes
#define FF   255      // feature dim
#define FF2  510      // 2*F
#define EE   65536    // edges
#define HH   2048     // hidden
#define OUTN 32640    // output
#define NF   65280    // N*F (flatten)

// ---------------- scratch (__device__ globals, no runtime alloc) -------------
__device__ __align__(16) float g_T[FF * FF2];       // W2 @ W1        [255,510]
__device__ __align__(16) float g_A3[FF * FF2];      // W3 @ T         [255,510]
__device__ __align__(16) float g_QP[FF2 * FF];      // [Q; P] rows    [510,255]
__device__ __align__(16) float g_cbig[FF2];         // [0...0, c]     [510]
__device__ __align__(16) float g_Cfull[NN * FF2];   // [Y | Z+c]      [256,510]
__device__ __align__(16) float g_gA[NN * FF];       // node feats ping
__device__ __align__(16) float g_gB[NN * FF];       // node feats pong
__device__ __align__(16) float g_y[HH];             // hidden vector
__device__ unsigned g_adj[NN * 8];                  // adjacency bitmask: bit j of row i => edge j->i

// ---------------- adjacency ----------------
__global__ void zero_adj_kernel(unsigned* adj) {
    int i = blockIdx.x * blockDim.x + threadIdx.x;
    if (i < NN * 8) adj[i] = 0u;
}

__global__ void scatter_adj_kernel(const int* __restrict__ ei, unsigned* __restrict__ adj) {
    int e = blockIdx.x * blockDim.x + threadIdx.x;
    if (e >= EE) return;
    int s = ei[e];          // src (j)
    int d = ei[EE + e];     // dst (i)
    atomicOr(&adj[(d << 3) + (s >> 5)], 1u << (s & 31));
}

// ---------------- small fp32 GEMMs (tiny shapes, perf non-critical) ----------
// C[M,N] = A[M,K] @ B[K,N] (+ bias[N])
__global__ void gemm_nn_kernel(const float* __restrict__ A, const float* __restrict__ B,
                               float* __restrict__ C, int M, int N, int K,
                               const float* __restrict__ bias) {
    __shared__ float As[16][16];
    __shared__ float Bs[16][17];
    int tx = threadIdx.x, ty = threadIdx.y;
    int row = blockIdx.y * 16 + ty;
    int col = blockIdx.x * 16 + tx;
    float acc = 0.f;
    for (int k0 = 0; k0 < K; k0 += 16) {
        As[ty][tx] = (row < M && k0 + tx < K) ? A[row * K + k0 + tx] : 0.f;
        Bs[ty][tx] = (k0 + ty < K && col < N) ? B[(k0 + ty) * N + col] : 0.f;
        __syncthreads();
#pragma unroll
        for (int k = 0; k < 16; k++) acc += As[ty][k] * Bs[k][tx];
        __syncthreads();
    }
    if (row < M && col < N) C[row * N + col] = acc + (bias ? bias[col] : 0.f);
}

// C[M,N] = A[M,K] @ B[N,K]^T (+ bias[N])   (B in [out,in] weight layout)
__global__ void gemm_nt_kernel(const float* __restrict__ A, const float* __restrict__ B,
                               float* __restrict__ C, int M, int N, int K,
                               const float* __restrict__ bias) {
    __shared__ float As[16][16];
    __shared__ float Bs[16][17];   // Bs[k][n]
    int tx = threadIdx.x, ty = threadIdx.y;
    int row = blockIdx.y * 16 + ty;
    int col = blockIdx.x * 16 + tx;
    float acc = 0.f;
    for (int k0 = 0; k0 < K; k0 += 16) {
        As[ty][tx] = (row < M && k0 + tx < K) ? A[row * K + k0 + tx] : 0.f;
        int bn = blockIdx.x * 16 + ty;
        int bk = k0 + tx;
        Bs[tx][ty] = (bn < N && bk < K) ? B[bn * K + bk] : 0.f;
        __syncthreads();
#pragma unroll
        for (int k = 0; k < 16; k++) acc += As[ty][k] * Bs[k][tx];
        __syncthreads();
    }
    if (row < M && col < N) C[row * N + col] = acc + (bias ? bias[col] : 0.f);
}

// ---------------- bias composition: c = W3(W2 b1 + b2) + b3 -> cbig ----------
__global__ void cvec_kernel(const float* __restrict__ W2, const float* __restrict__ b1,
                            const float* __restrict__ b2, const float* __restrict__ W3,
                            const float* __restrict__ b3, float* __restrict__ cbig) {
    __shared__ float u[FF];
    int t = threadIdx.x;  // 256 threads
    if (t < FF) {
        float s = b2[t];
        for (int k = 0; k < FF2; k++) s += W2[t * FF2 + k] * b1[k];
        u[t] = s;
    }
    __syncthreads();
    if (t < FF) {
        float s = b3[t];
        for (int k = 0; k < FF; k++) s += W3[t * FF + k] * u[k];
        cbig[FF + t] = s;   // Z part gets c
        cbig[t] = 0.f;      // Y part gets 0
    }
}

// ---------------- build QP from A3 = [A1 | A2]: Q = A2, P = A1 - A2 ----------
__global__ void build_qp_kernel(const float* __restrict__ A3, float* __restrict__ QP) {
    int idx = blockIdx.x * blockDim.x + threadIdx.x;
    if (idx >= FF2 * FF) return;
    int f = idx / FF, i = idx - f * FF;
    if (f < FF) {
        QP[idx] = A3[f * FF2 + FF + i];                       // Q row
    } else {
        int fr = f - FF;
        QP[idx] = A3[fr * FF2 + i] - A3[fr * FF2 + FF + i];   // P row
    }
}

// ---------------- masked segment-max + combine + relu (+residual) ------------
// Cfull[j][0:255]   = Y[j] = Q @ x_j
// Cfull[i][255:510] = Z[i] = P @ x_i + c
// gout[i][f] = relu( (empty(i) ? 0 : Z[i][f] + max_{j in nb(i)} Y[j][f]) + res[i][f] )
__global__ void maxcombine_kernel(const float* __restrict__ Cfull,
                                  const unsigned* __restrict__ adj,
                                  const float* __restrict__ res,
                                  float* __restrict__ gout) {
    int i = blockIdx.x;
    int f = threadIdx.x;
    __shared__ unsigned row[8];
    if (threadIdx.x < 8) row[threadIdx.x] = adj[(i << 3) + threadIdx.x];
    __syncthreads();
    unsigned any = row[0] | row[1] | row[2] | row[3] | row[4] | row[5] | row[6] | row[7];
    if (f >= FF) return;

    float u = -FLT_MAX;
#pragma unroll 4
    for (int j = 0; j < NN; j++) {
        unsigned w = row[j >> 5];
        if ((w >> (j & 31)) & 1u) {
            u = fmaxf(u, Cfull[j * FF2 + f]);
        }
    }
    float agg = (any == 0u) ? 0.f : (Cfull[i * FF2 + FF + f] + u);
    float r = res ? res[i * FF + f] : 0.f;
    gout[i * FF + f] = fmaxf(agg + r, 0.f);
}

// ---------------- y = relu(l4_W @ g3flat + l4_b)  (2048 x 65280 matvec) ------
__global__ void matvec_l4_kernel(const float* __restrict__ W, const float* __restrict__ b,
                                 const float* __restrict__ x, float* __restrict__ y) {
    int h = blockIdx.x;
    const float4* Wr = reinterpret_cast<const float4*>(W + (size_t)h * NF);
    const float4* xr = reinterpret_cast<const float4*>(x);
    float acc = 0.f;
#pragma unroll 4
    for (int k = threadIdx.x; k < NF / 4; k += 256) {
        float4 w = Wr[k];
        float4 v = xr[k];
        acc += w.x * v.x + w.y * v.y + w.z * v.z + w.w * v.w;
    }
    __shared__ float red[256];
    red[threadIdx.x] = acc;
    __syncthreads();
    for (int s = 128; s > 0; s >>= 1) {
        if (threadIdx.x < s) red[threadIdx.x] += red[threadIdx.x + s];
        __syncthreads();
    }
    if (threadIdx.x == 0) y[h] = fmaxf(red[0] + b[h], 0.f);
}

// ---------------- out = out_W @ y + out_b  (32640 x 2048, warp per row) ------
__global__ void matvec_out_kernel(const float* __restrict__ W, const float* __restrict__ b,
                                  const float* __restrict__ y, float* __restrict__ out) {
    int warp = threadIdx.x >> 5;
    int lane = threadIdx.x & 31;
    int row = blockIdx.x * 8 + warp;   // 4080 blocks * 8 warps = 32640 rows
    const float4* Wr = reinterpret_cast<const float4*>(W + (size_t)row * HH);
    const float4* yr = reinterpret_cast<const float4*>(y);
    float acc = 0.f;
#pragma unroll
    for (int k = lane; k < HH / 4; k += 32) {
        float4 w = Wr[k];
        float4 v = yr[k];
        acc += w.x * v.x + w.y * v.y + w.z * v.z + w.w * v.w;
    }
#pragma unroll
    for (int o = 16; o > 0; o >>= 1) acc += __shfl_down_sync(0xffffffffu, acc, o);
    if (lane == 0) out[row] = acc + b[row];
}

// =============================================================================
extern "C" void kernel_launch(void* const* d_in, const int* in_sizes, int n_in,
                              void* d_out, int out_size) {
    const float* x  = (const float*)d_in[0];
    const int*   ei = (const int*)d_in[1];

    // ec{1,2,3}_{W1,b1,W2,b2,W3,b3} at indices 2..19
    const float* W[3][3];
    const float* B[3][3];
    int idx = 2;
    for (int l = 0; l < 3; l++) {
        for (int m = 0; m < 3; m++) {
            W[l][m] = (const float*)d_in[idx++];
            B[l][m] = (const float*)d_in[idx++];
        }
    }
    const float* l4W  = (const float*)d_in[20];
    const float* l4b  = (const float*)d_in[21];
    const float* outW = (const float*)d_in[22];
    const float* outb = (const float*)d_in[23];
    float* out = (float*)d_out;

    float *T, *A3, *QP, *cbig, *Cfull, *gA, *gB, *y;
    unsigned* adj;
    cudaGetSymbolAddress((void**)&T,     g_T);
    cudaGetSymbolAddress((void**)&A3,    g_A3);
    cudaGetSymbolAddress((void**)&QP,    g_QP);
    cudaGetSymbolAddress((void**)&cbig,  g_cbig);
    cudaGetSymbolAddress((void**)&Cfull, g_Cfull);
    cudaGetSymbolAddress((void**)&gA,    g_gA);
    cudaGetSymbolAddress((void**)&gB,    g_gB);
    cudaGetSymbolAddress((void**)&y,     g_y);
    cudaGetSymbolAddress((void**)&adj,   g_adj);

    dim3 blk(16, 16);

    // adjacency bitmask (same for all three layers)
    zero_adj_kernel<<<8, 256>>>(adj);
    scatter_adj_kernel<<<EE / 256, 256>>>(ei, adj);

    const float* gin = x;
    for (int l = 0; l < 3; l++) {
        // T = W2 @ W1 : [255,510] = [255,510] @ [510,510]
        {
            dim3 grid((FF2 + 15) / 16, (FF + 15) / 16);
            gemm_nn_kernel<<<grid, blk>>>(W[l][1], W[l][0], T, FF, FF2, FF2, nullptr);
        }
        // A3 = W3 @ T : [255,510] = [255,255] @ [255,510]
        {
            dim3 grid((FF2 + 15) / 16, (FF + 15) / 16);
            gemm_nn_kernel<<<grid, blk>>>(W[l][2], T, A3, FF, FF2, FF, nullptr);
        }
        // cbig = [0, c],  c = W3(W2 b1 + b2) + b3
        cvec_kernel<<<1, 256>>>(W[l][1], B[l][0], B[l][1], W[l][2], B[l][2], cbig);
        // QP = [Q; P]
        build_qp_kernel<<<(FF2 * FF + 255) / 256, 256>>>(A3, QP);
        // Cfull = gin @ QP^T + cbig : [256,510]
        {
            dim3 grid((FF2 + 15) / 16, (NN + 15) / 16);
            gemm_nt_kernel<<<grid, blk>>>(gin, QP, Cfull, NN, FF2, FF, cbig);
        }
        // segment-max + combine + relu (+ residual for layers 2,3)
        const float* res = (l == 0) ? nullptr : gin;
        float* gout = (l == 1) ? gB : gA;
        maxcombine_kernel<<<NN, 256>>>(Cfull, adj, res, gout);
        gin = gout;
    }

    // y = relu(l4_W @ g3flat + l4_b)
    matvec_l4_kernel<<<HH, 256>>>(l4W, l4b, gin, y);
    // out = out_W @ y + out_b
    matvec_out_kernel<<<OUTN / 8, 256>>>(outW, outb, y, out);
}